// round 15
// baseline (speedup 1.0000x reference)
#include <cuda_runtime.h>
#include <cstdint>

// Problem shape (fixed by the dataset): x is [128, 1, 512, 512] fp32 -> 128 rows x 262144.
#define ROWS     128
#define BINS1    2048      // top 11 bits of absbits (bit31 is 0 after abs-mask)
#define SLICES   8         // blocks per row for the streaming kernels
#define CAND_MAX 65536     // per-row candidate capacity (expected ~1700)
#define SCAP     8192      // smem candidate cache in refine kernel
#define TIE_CAP  512

// ---- static device scratch (no allocations allowed) ----
__device__ unsigned int g_hist[ROWS * BINS1];                       // 1 MB
__device__ unsigned int g_cand[(size_t)ROWS * CAND_MAX];            // 32 MB
__device__ unsigned int g_candcnt[ROWS];
__device__ unsigned int g_bin1[ROWS];
__device__ unsigned int g_need1[ROWS];

// -------------------------------------------------------------------------
// Hillis-Steele block-wide suffix sum over NB shared entries (a,b ping-pong).
// Caller must __syncthreads() after filling a. Returns pointer holding result.
// -------------------------------------------------------------------------
template <int NB>
__device__ unsigned int* block_suffix(unsigned int* a, unsigned int* b) {
    unsigned int* src = a;
    unsigned int* dst = b;
    for (int off = 1; off < NB; off <<= 1) {
        for (int i = threadIdx.x; i < NB; i += blockDim.x) {
            unsigned int v = src[i];
            if (i + off < NB) v += src[i + off];
            dst[i] = v;
        }
        __syncthreads();
        unsigned int* t = src; src = dst; dst = t;
    }
    return src;
}

// -------------------------------------------------------------------------
// K0: zero the scratch that gets atomically accumulated (deterministic replay)
// -------------------------------------------------------------------------
__global__ void k_init() {
    int i = blockIdx.x * blockDim.x + threadIdx.x;
    if (i < ROWS * BINS1) g_hist[i] = 0u;
    if (i < ROWS) g_candcnt[i] = 0u;
}

// -------------------------------------------------------------------------
// K1: per-row histogram of absbits>>20 (2048 bins). 8 blocks per row.
// -------------------------------------------------------------------------
__global__ void k_hist(const float* __restrict__ x, int N) {
    int row = blockIdx.x / SLICES;
    int sl  = blockIdx.x % SLICES;

    __shared__ unsigned int sh[BINS1];
    for (int i = threadIdx.x; i < BINS1; i += blockDim.x) sh[i] = 0u;
    __syncthreads();

    int nvec = N >> 2;             // float4 per row
    int svec = nvec / SLICES;      // float4 per block
    const float4* xr = reinterpret_cast<const float4*>(x)
                     + (size_t)row * nvec + (size_t)sl * svec;

    for (int i = threadIdx.x; i < svec; i += blockDim.x) {
        float4 v = xr[i];
        atomicAdd(&sh[(__float_as_uint(v.x) & 0x7FFFFFFFu) >> 20], 1u);
        atomicAdd(&sh[(__float_as_uint(v.y) & 0x7FFFFFFFu) >> 20], 1u);
        atomicAdd(&sh[(__float_as_uint(v.z) & 0x7FFFFFFFu) >> 20], 1u);
        atomicAdd(&sh[(__float_as_uint(v.w) & 0x7FFFFFFFu) >> 20], 1u);
    }
    __syncthreads();

    unsigned int* gh = g_hist + (size_t)row * BINS1;
    for (int i = threadIdx.x; i < BINS1; i += blockDim.x)
        if (sh[i]) atomicAdd(&gh[i], sh[i]);
}

// -------------------------------------------------------------------------
// K2: per-row suffix scan of the level-1 histogram -> threshold bin + need
// -------------------------------------------------------------------------
__global__ void k_pick(const int* __restrict__ kptr) {
    int row = blockIdx.x;
    __shared__ unsigned int a[BINS1];
    __shared__ unsigned int b[BINS1];
    __shared__ int s_bin;
    __shared__ unsigned int s_need;

    if (threadIdx.x == 0) { s_bin = 0; s_need = 1u; }
    const unsigned int* gh = g_hist + (size_t)row * BINS1;
    for (int i = threadIdx.x; i < BINS1; i += blockDim.x) a[i] = gh[i];
    __syncthreads();

    unsigned int* suf = block_suffix<BINS1>(a, b);
    unsigned int k = kptr ? (unsigned int)(*kptr) : 2048u;

    for (int i = threadIdx.x; i < BINS1; i += blockDim.x) {
        unsigned int here = suf[i];
        unsigned int nxt  = (i + 1 < BINS1) ? suf[i + 1] : 0u;
        if (here >= k && nxt < k) { s_bin = i; s_need = k - nxt; }
    }
    __syncthreads();
    if (threadIdx.x == 0) {
        g_bin1[row]  = (unsigned int)s_bin;
        g_need1[row] = s_need;
    }
}

// -------------------------------------------------------------------------
// K3: write decided outputs (streaming stores), compact threshold-bin
//     candidates (indices) to global scratch.
// -------------------------------------------------------------------------
__global__ void k_part(const float* __restrict__ x, float* __restrict__ out, int N) {
    int row = blockIdx.x / SLICES;
    int sl  = blockIdx.x % SLICES;
    unsigned int b1 = g_bin1[row];

    int nvec = N >> 2;
    int svec = nvec / SLICES;
    size_t base = (size_t)row * nvec + (size_t)sl * svec;
    const float4* xr  = reinterpret_cast<const float4*>(x) + base;
    float4*       owr = reinterpret_cast<float4*>(out) + base;
    unsigned int* cidx = g_cand + (size_t)row * CAND_MAX;

    for (int i = threadIdx.x; i < svec; i += blockDim.x) {
        float4 v = xr[i];
        int j0 = (sl * svec + i) << 2;   // element index within row
        float vi[4] = {v.x, v.y, v.z, v.w};
        float oo[4];
#pragma unroll
        for (int c = 0; c < 4; c++) {
            unsigned int bb  = __float_as_uint(vi[c]) & 0x7FFFFFFFu;
            unsigned int bin = bb >> 20;
            float o = 0.0f;
            if (bin > b1) {
                o = vi[c];
            } else if (bin == b1) {
                unsigned int pos = atomicAdd(&g_candcnt[row], 1u);
                if (pos < CAND_MAX) cidx[pos] = (unsigned int)(j0 + c);
            }
            oo[c] = o;
        }
        __stcs(owr + i, make_float4(oo[0], oo[1], oo[2], oo[3]));
    }
}

// -------------------------------------------------------------------------
// K4: per-row refine over candidates (two 1024-bin radix passes -> exact
//     32-bit threshold T), then scatter kept candidates. Exact-bit ties at
//     T are broken by LOWEST index (matches jax.lax.top_k stability).
// -------------------------------------------------------------------------
__global__ void k_refine(const float* __restrict__ x, float* __restrict__ out, int N) {
    int row = blockIdx.x;
    __shared__ unsigned int sh_bits[SCAP];
    __shared__ unsigned int h1[1024];
    __shared__ unsigned int h2[1024];
    __shared__ unsigned int s_ties[TIE_CAP];
    __shared__ unsigned int s_tiecnt;
    __shared__ int s_b;
    __shared__ unsigned int s_need;

    unsigned int cnt = g_candcnt[row];
    if (cnt > CAND_MAX) cnt = CAND_MAX;
    unsigned int need = g_need1[row];
    unsigned int b1   = g_bin1[row];
    const unsigned int* cidx = g_cand + (size_t)row * CAND_MAX;
    const float* xr   = x   + (size_t)row * N;
    float*       orow = out + (size_t)row * N;
    bool in_s = (cnt <= SCAP);

    if (threadIdx.x == 0) { s_tiecnt = 0u; s_b = 0; s_need = 1u; }
    for (int i = threadIdx.x; i < 1024; i += blockDim.x) h1[i] = 0u;
    __syncthreads();

    // ---- level 2: bits[19:10] ----
    for (int i = threadIdx.x; i < (int)cnt; i += blockDim.x) {
        unsigned int bb = __float_as_uint(xr[cidx[i]]) & 0x7FFFFFFFu;
        if (in_s) sh_bits[i] = bb;
        atomicAdd(&h1[(bb >> 10) & 1023u], 1u);
    }
    __syncthreads();
    unsigned int* suf = block_suffix<1024>(h1, h2);
    for (int i = threadIdx.x; i < 1024; i += blockDim.x) {
        unsigned int here = suf[i];
        unsigned int nxt  = (i + 1 < 1024) ? suf[i + 1] : 0u;
        if (here >= need && nxt < need) { s_b = i; s_need = need - nxt; }
    }
    __syncthreads();
    unsigned int b2    = (unsigned int)s_b;
    unsigned int need2 = s_need;
    __syncthreads();

    // ---- level 3: bits[9:0] among b2 matches ----
    for (int i = threadIdx.x; i < 1024; i += blockDim.x) h1[i] = 0u;
    __syncthreads();
    for (int i = threadIdx.x; i < (int)cnt; i += blockDim.x) {
        unsigned int bb = in_s ? sh_bits[i]
                               : (__float_as_uint(xr[cidx[i]]) & 0x7FFFFFFFu);
        if (((bb >> 10) & 1023u) == b2) atomicAdd(&h1[bb & 1023u], 1u);
    }
    __syncthreads();
    suf = block_suffix<1024>(h1, h2);
    for (int i = threadIdx.x; i < 1024; i += blockDim.x) {
        unsigned int here = suf[i];
        unsigned int nxt  = (i + 1 < 1024) ? suf[i + 1] : 0u;
        if (here >= need2 && nxt < need2) { s_b = i; s_need = need2 - nxt; }
    }
    __syncthreads();
    unsigned int b3    = (unsigned int)s_b;
    unsigned int need3 = s_need;
    unsigned int tie_total = suf[b3] - ((b3 + 1 < 1024) ? suf[b3 + 1] : 0u);
    unsigned int T = (b1 << 20) | (b2 << 10) | b3;

    // ---- scatter kept candidates ----
    for (int i = threadIdx.x; i < (int)cnt; i += blockDim.x) {
        unsigned int id = cidx[i];
        float v = xr[id];
        unsigned int bb = __float_as_uint(v) & 0x7FFFFFFFu;
        if (bb > T) {
            orow[id] = v;
        } else if (bb == T) {
            if (need3 == tie_total) {
                orow[id] = v;            // all ties kept, order irrelevant
            } else {
                unsigned int t = atomicAdd(&s_tiecnt, 1u);
                if (t < TIE_CAP) s_ties[t] = id;
            }
        }
    }
    __syncthreads();

    // partial-ties case: keep the need3 LOWEST indices (stable like jax top_k)
    if (threadIdx.x == 0 && need3 != tie_total) {
        unsigned int tt = s_tiecnt; if (tt > TIE_CAP) tt = TIE_CAP;
        unsigned int nsel = (need3 < tt) ? need3 : tt;
        for (unsigned int s = 0; s < nsel; s++) {
            unsigned int best = s;
            for (unsigned int j = s + 1; j < tt; j++)
                if (s_ties[j] < s_ties[best]) best = j;
            unsigned int tmp = s_ties[s]; s_ties[s] = s_ties[best]; s_ties[best] = tmp;
            unsigned int id = s_ties[s];
            orow[id] = xr[id];
        }
    }
}

// -------------------------------------------------------------------------
extern "C" void kernel_launch(void* const* d_in, const int* in_sizes, int n_in,
                              void* d_out, int out_size) {
    const float* x = (const float*)d_in[0];
    const int* kptr = (n_in >= 2) ? (const int*)d_in[1] : nullptr;
    float* out = (float*)d_out;

    int total = in_sizes[0];
    int N = total / ROWS;   // 262144 for this dataset

    k_init<<<(ROWS * BINS1 + 255) / 256, 256>>>();
    k_hist<<<ROWS * SLICES, 512>>>(x, N);
    k_pick<<<ROWS, 1024>>>(kptr);
    k_part<<<ROWS * SLICES, 512>>>(x, out, N);
    k_refine<<<ROWS, 1024>>>(x, out, N);
}

// round 16
// speedup vs baseline: 1.6345x; 1.6345x over previous
#include <cuda_runtime.h>
#include <cstdint>

// Problem shape (fixed by the dataset): x is [128, 1, 512, 512] fp32 -> 128 rows x 262144.
#define ROWS     128
#define BINS1    2048      // top 11 bits of absbits (bit31 is 0 after abs-mask)
#define SLICES   8         // blocks per row for the streaming kernels
#define CAND_MAX 65536     // per-row candidate capacity (expected ~1700)
#define SCAP     8192      // smem candidate cache in refine kernel
#define TIE_CAP  512
#define PCAP     4096      // per-block smem candidate staging in k_part

// ---- static device scratch (no allocations allowed) ----
__device__ unsigned int g_hist[ROWS * BINS1];                       // 1 MB
__device__ unsigned int g_cand[(size_t)ROWS * CAND_MAX];            // 32 MB
__device__ unsigned int g_candcnt[ROWS];
__device__ unsigned int g_bin1[ROWS];
__device__ unsigned int g_need1[ROWS];

// -------------------------------------------------------------------------
// Hillis-Steele block-wide suffix sum over NB shared entries (a,b ping-pong).
// Caller must __syncthreads() after filling a. Returns pointer holding result.
// -------------------------------------------------------------------------
template <int NB>
__device__ unsigned int* block_suffix(unsigned int* a, unsigned int* b) {
    unsigned int* src = a;
    unsigned int* dst = b;
    for (int off = 1; off < NB; off <<= 1) {
        for (int i = threadIdx.x; i < NB; i += blockDim.x) {
            unsigned int v = src[i];
            if (i + off < NB) v += src[i + off];
            dst[i] = v;
        }
        __syncthreads();
        unsigned int* t = src; src = dst; dst = t;
    }
    return src;
}

// -------------------------------------------------------------------------
// K0: zero the scratch that gets atomically accumulated (deterministic replay)
// -------------------------------------------------------------------------
__global__ void k_init() {
    int i = blockIdx.x * blockDim.x + threadIdx.x;
    if (i < ROWS * BINS1) g_hist[i] = 0u;
    if (i < ROWS) g_candcnt[i] = 0u;
}

// -------------------------------------------------------------------------
// K1: per-row histogram of absbits>>20 (2048 bins). 8 blocks per row.
// 4-way batched loads for MLP; smem atomics (spread bins, low conflict).
// -------------------------------------------------------------------------
__global__ void k_hist(const float* __restrict__ x, int N) {
    int row = blockIdx.x / SLICES;
    int sl  = blockIdx.x % SLICES;

    __shared__ unsigned int sh[BINS1];
    for (int i = threadIdx.x; i < BINS1; i += blockDim.x) sh[i] = 0u;
    __syncthreads();

    int nvec = N >> 2;             // float4 per row
    int svec = nvec / SLICES;      // float4 per block
    const float4* xr = reinterpret_cast<const float4*>(x)
                     + (size_t)row * nvec + (size_t)sl * svec;

    const int T = blockDim.x;
    for (int i0 = threadIdx.x; i0 < svec; i0 += 4 * T) {
        float4 v[4];
        int have = 0;
#pragma unroll
        for (int u = 0; u < 4; u++) {
            int i = i0 + u * T;
            if (i < svec) { v[u] = xr[i]; have = u + 1; }
        }
#pragma unroll
        for (int u = 0; u < 4; u++) {
            if (u < have) {
                atomicAdd(&sh[(__float_as_uint(v[u].x) & 0x7FFFFFFFu) >> 20], 1u);
                atomicAdd(&sh[(__float_as_uint(v[u].y) & 0x7FFFFFFFu) >> 20], 1u);
                atomicAdd(&sh[(__float_as_uint(v[u].z) & 0x7FFFFFFFu) >> 20], 1u);
                atomicAdd(&sh[(__float_as_uint(v[u].w) & 0x7FFFFFFFu) >> 20], 1u);
            }
        }
    }
    __syncthreads();

    unsigned int* gh = g_hist + (size_t)row * BINS1;
    for (int i = threadIdx.x; i < BINS1; i += blockDim.x)
        if (sh[i]) atomicAdd(&gh[i], sh[i]);
}

// -------------------------------------------------------------------------
// K2: per-row suffix scan of the level-1 histogram -> threshold bin + need
// -------------------------------------------------------------------------
__global__ void k_pick(const int* __restrict__ kptr) {
    int row = blockIdx.x;
    __shared__ unsigned int a[BINS1];
    __shared__ unsigned int b[BINS1];
    __shared__ int s_bin;
    __shared__ unsigned int s_need;

    if (threadIdx.x == 0) { s_bin = 0; s_need = 1u; }
    const unsigned int* gh = g_hist + (size_t)row * BINS1;
    for (int i = threadIdx.x; i < BINS1; i += blockDim.x) a[i] = gh[i];
    __syncthreads();

    unsigned int* suf = block_suffix<BINS1>(a, b);
    unsigned int k = kptr ? (unsigned int)(*kptr) : 2048u;

    for (int i = threadIdx.x; i < BINS1; i += blockDim.x) {
        unsigned int here = suf[i];
        unsigned int nxt  = (i + 1 < BINS1) ? suf[i + 1] : 0u;
        if (here >= k && nxt < k) { s_bin = i; s_need = k - nxt; }
    }
    __syncthreads();
    if (threadIdx.x == 0) {
        g_bin1[row]  = (unsigned int)s_bin;
        g_need1[row] = s_need;
    }
}

// -------------------------------------------------------------------------
// K3: write decided outputs (streaming stores), stage threshold-bin
//     candidate indices in SMEM, reserve a contiguous global range with ONE
//     atomicAdd per block, bulk-copy out. Candidate order is irrelevant
//     (k_refine breaks exact-bit ties by index VALUE, not arrival order).
// -------------------------------------------------------------------------
__global__ void k_part(const float* __restrict__ x, float* __restrict__ out, int N) {
    int row = blockIdx.x / SLICES;
    int sl  = blockIdx.x % SLICES;
    unsigned int b1 = g_bin1[row];

    __shared__ unsigned int s_idx[PCAP];
    __shared__ unsigned int s_cnt;
    __shared__ unsigned int s_base;
    if (threadIdx.x == 0) s_cnt = 0u;
    __syncthreads();

    int nvec = N >> 2;
    int svec = nvec / SLICES;
    size_t base = (size_t)row * nvec + (size_t)sl * svec;
    const float4* xr  = reinterpret_cast<const float4*>(x) + base;
    float4*       owr = reinterpret_cast<float4*>(out) + base;
    unsigned int* cidx = g_cand + (size_t)row * CAND_MAX;

    const int T = blockDim.x;
    for (int i0 = threadIdx.x; i0 < svec; i0 += 4 * T) {
        float4 v[4];
#pragma unroll
        for (int u = 0; u < 4; u++) {
            int i = i0 + u * T;
            if (i < svec) v[u] = xr[i];      // 4 independent LDG.128 in flight
        }
#pragma unroll
        for (int u = 0; u < 4; u++) {
            int i = i0 + u * T;
            if (i >= svec) continue;
            int j0 = (sl * svec + i) << 2;   // element index within row
            float vi[4] = {v[u].x, v[u].y, v[u].z, v[u].w};
            float oo[4];
#pragma unroll
            for (int c = 0; c < 4; c++) {
                unsigned int bb  = __float_as_uint(vi[c]) & 0x7FFFFFFFu;
                unsigned int bin = bb >> 20;
                float o = 0.0f;
                if (bin > b1) {
                    o = vi[c];
                } else if (bin == b1) {
                    unsigned int p = atomicAdd(&s_cnt, 1u);   // smem, lat~30
                    if (p < PCAP) {
                        s_idx[p] = (unsigned int)(j0 + c);
                    } else {                                   // overflow (never expected)
                        unsigned int gp = atomicAdd(&g_candcnt[row], 1u);
                        if (gp < CAND_MAX) cidx[gp] = (unsigned int)(j0 + c);
                    }
                }
                oo[c] = o;
            }
            __stcs(owr + i, make_float4(oo[0], oo[1], oo[2], oo[3]));
        }
    }
    __syncthreads();

    unsigned int c = s_cnt; if (c > PCAP) c = PCAP;
    if (threadIdx.x == 0)
        s_base = atomicAdd(&g_candcnt[row], c);   // ONE global atomic per block
    __syncthreads();
    unsigned int gb = s_base;
    for (unsigned int i = threadIdx.x; i < c; i += blockDim.x)
        if (gb + i < CAND_MAX) cidx[gb + i] = s_idx[i];
}

// -------------------------------------------------------------------------
// K4: per-row refine over candidates (two 1024-bin radix passes -> exact
//     32-bit threshold T), then scatter kept candidates. Exact-bit ties at
//     T are broken by LOWEST index (matches jax.lax.top_k stability).
// -------------------------------------------------------------------------
__global__ void k_refine(const float* __restrict__ x, float* __restrict__ out, int N) {
    int row = blockIdx.x;
    __shared__ unsigned int sh_bits[SCAP];
    __shared__ unsigned int h1[1024];
    __shared__ unsigned int h2[1024];
    __shared__ unsigned int s_ties[TIE_CAP];
    __shared__ unsigned int s_tiecnt;
    __shared__ int s_b;
    __shared__ unsigned int s_need;

    unsigned int cnt = g_candcnt[row];
    if (cnt > CAND_MAX) cnt = CAND_MAX;
    unsigned int need = g_need1[row];
    unsigned int b1   = g_bin1[row];
    const unsigned int* cidx = g_cand + (size_t)row * CAND_MAX;
    const float* xr   = x   + (size_t)row * N;
    float*       orow = out + (size_t)row * N;
    bool in_s = (cnt <= SCAP);

    if (threadIdx.x == 0) { s_tiecnt = 0u; s_b = 0; s_need = 1u; }
    for (int i = threadIdx.x; i < 1024; i += blockDim.x) h1[i] = 0u;
    __syncthreads();

    // ---- level 2: bits[19:10] ----
    for (int i = threadIdx.x; i < (int)cnt; i += blockDim.x) {
        unsigned int bb = __float_as_uint(xr[cidx[i]]) & 0x7FFFFFFFu;
        if (in_s) sh_bits[i] = bb;
        atomicAdd(&h1[(bb >> 10) & 1023u], 1u);
    }
    __syncthreads();
    unsigned int* suf = block_suffix<1024>(h1, h2);
    for (int i = threadIdx.x; i < 1024; i += blockDim.x) {
        unsigned int here = suf[i];
        unsigned int nxt  = (i + 1 < 1024) ? suf[i + 1] : 0u;
        if (here >= need && nxt < need) { s_b = i; s_need = need - nxt; }
    }
    __syncthreads();
    unsigned int b2    = (unsigned int)s_b;
    unsigned int need2 = s_need;
    __syncthreads();

    // ---- level 3: bits[9:0] among b2 matches ----
    for (int i = threadIdx.x; i < 1024; i += blockDim.x) h1[i] = 0u;
    __syncthreads();
    for (int i = threadIdx.x; i < (int)cnt; i += blockDim.x) {
        unsigned int bb = in_s ? sh_bits[i]
                               : (__float_as_uint(xr[cidx[i]]) & 0x7FFFFFFFu);
        if (((bb >> 10) & 1023u) == b2) atomicAdd(&h1[bb & 1023u], 1u);
    }
    __syncthreads();
    suf = block_suffix<1024>(h1, h2);
    for (int i = threadIdx.x; i < 1024; i += blockDim.x) {
        unsigned int here = suf[i];
        unsigned int nxt  = (i + 1 < 1024) ? suf[i + 1] : 0u;
        if (here >= need2 && nxt < need2) { s_b = i; s_need = need2 - nxt; }
    }
    __syncthreads();
    unsigned int b3    = (unsigned int)s_b;
    unsigned int need3 = s_need;
    unsigned int tie_total = suf[b3] - ((b3 + 1 < 1024) ? suf[b3 + 1] : 0u);
    unsigned int T = (b1 << 20) | (b2 << 10) | b3;

    // ---- scatter kept candidates ----
    for (int i = threadIdx.x; i < (int)cnt; i += blockDim.x) {
        unsigned int id = cidx[i];
        float v = xr[id];
        unsigned int bb = __float_as_uint(v) & 0x7FFFFFFFu;
        if (bb > T) {
            orow[id] = v;
        } else if (bb == T) {
            if (need3 == tie_total) {
                orow[id] = v;            // all ties kept, order irrelevant
            } else {
                unsigned int t = atomicAdd(&s_tiecnt, 1u);
                if (t < TIE_CAP) s_ties[t] = id;
            }
        }
    }
    __syncthreads();

    // partial-ties case: keep the need3 LOWEST indices (stable like jax top_k)
    if (threadIdx.x == 0 && need3 != tie_total) {
        unsigned int tt = s_tiecnt; if (tt > TIE_CAP) tt = TIE_CAP;
        unsigned int nsel = (need3 < tt) ? need3 : tt;
        for (unsigned int s = 0; s < nsel; s++) {
            unsigned int best = s;
            for (unsigned int j = s + 1; j < tt; j++)
                if (s_ties[j] < s_ties[best]) best = j;
            unsigned int tmp = s_ties[s]; s_ties[s] = s_ties[best]; s_ties[best] = tmp;
            unsigned int id = s_ties[s];
            orow[id] = xr[id];
        }
    }
}

// -------------------------------------------------------------------------
extern "C" void kernel_launch(void* const* d_in, const int* in_sizes, int n_in,
                              void* d_out, int out_size) {
    const float* x = (const float*)d_in[0];
    const int* kptr = (n_in >= 2) ? (const int*)d_in[1] : nullptr;
    float* out = (float*)d_out;

    int total = in_sizes[0];
    int N = total / ROWS;   // 262144 for this dataset

    k_init<<<(ROWS * BINS1 + 255) / 256, 256>>>();
    k_hist<<<ROWS * SLICES, 512>>>(x, N);
    k_pick<<<ROWS, 1024>>>(kptr);
    k_part<<<ROWS * SLICES, 512>>>(x, out, N);
    k_refine<<<ROWS, 1024>>>(x, out, N);
}